// round 14
// baseline (speedup 1.0000x reference)
#include <cuda_runtime.h>
#include <cuda_bf16.h>
#include <math.h>
#include <stdint.h>

// Gate_90426241450822: logits = x @ W ; y = softmax(logits) * top2_mask
// x: [M=16384, K=4096] fp32, W: [K=4096, E=64] fp32
// out: [y (M*64) | logits (M*64)] fp32
//
// R14: HMMA bf16 3-split GEMM, BM=64, 512 threads (4M x 2K x 2N warps),
// 2 CTAs/SM. NEW: per-tile smem convert phase — A lands raw fp32 (cp.async,
// 2-stage ring), 16 warps split disjoint 16x16 slices to bf16 hi/lo smem
// (one convert per element), consumers use pure ldmatrix for A (R9-validated
// fragment path). B pre-split bf16 in a 3-stage ring. Epilogue (top-3 +
// exact fp64 rescue margin<1e-4 + 1.2e-6 inversion window) unchanged.

#define KDIM 4096
#define EXP 64
#define BM 64
#define BK 64
#define NT (KDIM / BK)        // 64 tiles
#define THREADS 512

#define MARGIN_EPS 1e-4f
#define INVERT_TAU 1.2e-6

// ---- smem layout (bytes) ----
#define A_F32_STG 16384                      // 64 rows x 256B, XOR-swizzled
#define OFF_AF(s) ((uint32_t)(s) * A_F32_STG)        // stages 0,1
#define B_ROWB 144
#define B_STG 18432                                   // hi+lo, 64 x 144B each
#define OFF_BHI(s) (32768u + (uint32_t)(s) * B_STG)   // stages 0,1,2
#define OFF_BLO(s) (OFF_BHI(s) + 9216u)
#define ABF_STRIDE 160                                // bank-clean bf16 stride
#define OFF_AHI_BF 88064u                             // 64 x 160B
#define OFF_ALO_BF 98304u
#define SMEM_TOTAL 108544

__device__ __nv_bfloat16 g_Whi[EXP * KDIM];
__device__ __nv_bfloat16 g_Wlo[EXP * KDIM];

__device__ __forceinline__ uint32_t smem_u32(const void* p) {
    uint32_t a;
    asm("{ .reg .u64 t; cvta.to.shared.u64 t, %1; cvt.u32.u64 %0, t; }"
        : "=r"(a) : "l"(p));
    return a;
}
__device__ __forceinline__ void cp16(uint32_t dst, const void* src) {
    asm volatile("cp.async.cg.shared.global [%0], [%1], 16;"
                 :: "r"(dst), "l"(src) : "memory");
}
#define CP_COMMIT() asm volatile("cp.async.commit_group;" ::: "memory")
#define CP_WAIT1()  asm volatile("cp.async.wait_group 1;" ::: "memory")
#define CP_WAIT0()  asm volatile("cp.async.wait_group 0;" ::: "memory")

__device__ __forceinline__ float4 lds_f4(uint32_t addr) {
    float4 v;
    asm volatile("ld.shared.v4.f32 {%0,%1,%2,%3}, [%4];"
                 : "=f"(v.x), "=f"(v.y), "=f"(v.z), "=f"(v.w) : "r"(addr));
    return v;
}
__device__ __forceinline__ void sts128(uint32_t addr, const uint32_t* r) {
    asm volatile("st.shared.v4.b32 [%0], {%1,%2,%3,%4};"
                 :: "r"(addr), "r"(r[0]), "r"(r[1]), "r"(r[2]), "r"(r[3])
                 : "memory");
}
__device__ __forceinline__ void ldsm_x4(uint32_t* r, uint32_t addr) {
    asm volatile("ldmatrix.sync.aligned.m8n8.x4.shared.b16 {%0,%1,%2,%3}, [%4];"
                 : "=r"(r[0]), "=r"(r[1]), "=r"(r[2]), "=r"(r[3]) : "r"(addr));
}
__device__ __forceinline__ void mma_bf16(float* c, const uint32_t* a,
                                         uint32_t b0, uint32_t b1) {
    asm volatile(
        "mma.sync.aligned.m16n8k16.row.col.f32.bf16.bf16.f32 "
        "{%0,%1,%2,%3}, {%4,%5,%6,%7}, {%8,%9}, {%0,%1,%2,%3};"
        : "+f"(c[0]), "+f"(c[1]), "+f"(c[2]), "+f"(c[3])
        : "r"(a[0]), "r"(a[1]), "r"(a[2]), "r"(a[3]), "r"(b0), "r"(b1));
}
__device__ __forceinline__ void split2(float fx, float fy,
                                       uint32_t& hi, uint32_t& lo) {
    uint32_t h;
    asm("cvt.rn.bf16x2.f32 %0, %1, %2;" : "=r"(h) : "f"(fy), "f"(fx));
    const float h0 = __uint_as_float(h << 16);
    const float h1 = __uint_as_float(h & 0xffff0000u);
    const float r0 = fx - h0;
    const float r1 = fy - h1;
    asm("cvt.rn.bf16x2.f32 %0, %1, %2;" : "=r"(lo) : "f"(r1), "f"(r0));
    hi = h;
}
__device__ __forceinline__ bool ranks_above(float v1, int i1, float v2, int i2) {
    return (v1 > v2) || (v1 == v2 && i1 < i2);
}

// ---- W prep: split fp32 -> bf16 hi/lo, transpose to [E][K] ----
__global__ void prep_W_kernel(const float* __restrict__ W) {
    int idx = blockIdx.x * blockDim.x + threadIdx.x;
    int e = idx >> 12;
    int k = idx & (KDIM - 1);
    float v = W[(size_t)k * EXP + e];
    __nv_bfloat16 h = __float2bfloat16(v);
    g_Whi[idx] = h;
    g_Wlo[idx] = __float2bfloat16(v - __bfloat162float(h));
}

__global__ __launch_bounds__(THREADS, 2)
void gate_hmma_kernel(const float* __restrict__ x,
                      const float* __restrict__ W,
                      float* __restrict__ y_out,
                      float* __restrict__ logits_out) {
    extern __shared__ __align__(16) char smem[];
    const uint32_t sb = smem_u32(smem);
    const int tid = threadIdx.x;
    const int wid = tid >> 5;
    const int lane = tid & 31;
    const int mwarp = wid & 3;             // rows mwarp*16 .. +15
    const int khalf = (wid >> 2) & 1;      // k-steps {0,1} or {2,3}
    const int nhalf = wid >> 3;            // cols 0-31 or 32-63
    const int block_row = blockIdx.x * BM;

    // ---- producer constants ----
    const int p_arow = tid >> 3;               // A: 8 threads/row (64 rows)
    const int p_acb = (tid & 7) * 2;           // 2 chunks each
    const float* p_asrc = x + (size_t)(block_row + p_arow) * KDIM + p_acb * 4;
    const uint32_t p_aswz = (uint32_t)((p_arow & 3) << 1);
    const uint32_t p_adst = (uint32_t)(p_arow * 256);

    const int p_be = tid >> 3;                 // expert 0..63
    const int p_bp = tid & 7;                  // chunk 0..7
    const __nv_bfloat16* p_bh = g_Whi + (size_t)p_be * KDIM + p_bp * 8;
    const __nv_bfloat16* p_bl = g_Wlo + (size_t)p_be * KDIM + p_bp * 8;
    const uint32_t p_bdst = (uint32_t)(p_be * B_ROWB + p_bp * 16);

    // ---- convert-phase constants: warp handles rows mwarp*16..+15,
    //      k-slice ks_c*16..+16 (ks_c in 0..3 over khalf,nhalf) ----
    const int ks_c = khalf * 2 + nhalf;
    const int conv_row = mwarp * 16 + (lane >> 1);
    const int conv_kq = lane & 1;              // low/high 8 of the 16 k
    const uint32_t conv_swz = (uint32_t)((conv_row & 3) << 1);
    const uint32_t c0 = (uint32_t)(ks_c * 4 + conv_kq * 2);
    const uint32_t conv_src0 =
        (uint32_t)(conv_row * 256) + ((c0 ^ conv_swz) << 4);
    const uint32_t conv_src1 =
        (uint32_t)(conv_row * 256) + (((c0 + 1) ^ conv_swz) << 4);
    const uint32_t conv_dst =
        (uint32_t)(conv_row * ABF_STRIDE + ks_c * 32 + conv_kq * 16);

    // ---- consumer constants ----
    const uint32_t a_ld =
        (uint32_t)((mwarp * 16 + (lane & 15)) * ABF_STRIDE + (lane >> 4) * 16);
    const int bg = lane >> 3;
    const uint32_t b_ldoff =
        (uint32_t)(((bg >> 1) * 8 + (lane & 7)) * B_ROWB + (bg & 1) * 16);

    float c[4][4];
#pragma unroll
    for (int i = 0; i < 4; ++i)
#pragma unroll
        for (int j = 0; j < 4; ++j) c[i][j] = 0.0f;

    auto issue_tile = [&](int t) {
        const int k0 = t * BK;
        const uint32_t af = sb + OFF_AF(t & 1);
        const float* asrc = p_asrc + k0;
#pragma unroll
        for (int j = 0; j < 2; ++j) {
            const uint32_t cidx = (uint32_t)(p_acb + j);
            cp16(af + p_adst + ((cidx ^ p_aswz) << 4), asrc + j * 4);
        }
        const int bs = t % 3;
        cp16(sb + OFF_BHI(bs) + p_bdst, p_bh + k0);
        cp16(sb + OFF_BLO(bs) + p_bdst, p_bl + k0);
        CP_COMMIT();
    };

    issue_tile(0);
    issue_tile(1);

    for (int t = 0; t < NT; ++t) {
        if (t + 1 < NT) CP_WAIT1(); else CP_WAIT0();
        __syncthreads();   // stage t ready; A-bf16 buffer free (prev ldsm done)

        // ---- convert phase: fp32 stage -> bf16 hi/lo smem ----
        {
            const uint32_t af = sb + OFF_AF(t & 1);
            const float4 fa = lds_f4(af + conv_src0);
            const float4 fb = lds_f4(af + conv_src1);
            uint32_t hi[4], lo[4];
            split2(fa.x, fa.y, hi[0], lo[0]);
            split2(fa.z, fa.w, hi[1], lo[1]);
            split2(fb.x, fb.y, hi[2], lo[2]);
            split2(fb.z, fb.w, hi[3], lo[3]);
            sts128(sb + OFF_AHI_BF + conv_dst, hi);
            sts128(sb + OFF_ALO_BF + conv_dst, lo);
        }
        __syncthreads();   // converts done; A fp32 stage free for overwrite

        if (t + 2 < NT) issue_tile(t + 2);

        // ---- MMA phase: pure ldmatrix feeds ----
        const int bs = t % 3;
#pragma unroll
        for (int kk = 0; kk < 2; ++kk) {
            const int ks = khalf * 2 + kk;
            uint32_t ahi[4], alo[4];
            ldsm_x4(ahi, sb + OFF_AHI_BF + a_ld + (uint32_t)(ks * 32));
            ldsm_x4(alo, sb + OFF_ALO_BF + a_ld + (uint32_t)(ks * 32));
#pragma unroll
            for (int npl = 0; npl < 2; ++npl) {
                const int np = nhalf * 2 + npl;
                uint32_t bh[4], bl[4];
                const uint32_t bo = b_ldoff + (uint32_t)(np * 16 * B_ROWB + ks * 32);
                ldsm_x4(bh, sb + OFF_BHI(bs) + bo);
                ldsm_x4(bl, sb + OFF_BLO(bs) + bo);
                mma_bf16(c[2 * npl],     ahi, bh[0], bh[1]);
                mma_bf16(c[2 * npl],     ahi, bl[0], bl[1]);
                mma_bf16(c[2 * npl],     alo, bh[0], bh[1]);
                mma_bf16(c[2 * npl + 1], ahi, bh[2], bh[3]);
                mma_bf16(c[2 * npl + 1], ahi, bl[2], bl[3]);
                mma_bf16(c[2 * npl + 1], alo, bh[2], bh[3]);
            }
        }
    }

    __syncthreads();   // before red overlay of stage smem

    // ---- dump partials: red1 = khalf0, red2 = khalf1 (stride 65) ----
    float* red1 = (float*)smem;                // 64 x 65 fp32
    float* red2 = red1 + 64 * 65;
    {
        float* buf = khalf ? red2 : red1;
        const int q = lane >> 2;
        const int eb = (lane & 3) * 2;
#pragma unroll
        for (int i = 0; i < 4; ++i)
#pragma unroll
            for (int j = 0; j < 4; ++j) {
                const int row = mwarp * 16 + q + ((j >> 1) << 3);
                const int col = nhalf * 32 + i * 8 + eb + (j & 1);
                buf[row * 65 + col] = c[i][j];
            }
    }
    __syncthreads();

    // ---- epilogue (R9-R13 validated) on warps 0-3 ----
    if (wid < 4) {
        const int q = lane >> 2;
        const int eb = (lane & 3) * 2;
#pragma unroll
        for (int h = 0; h < 2; ++h) {
            const int row = wid * 16 + q + h * 8;
            const int row_g = block_row + row;
            float v[16];
#pragma unroll
            for (int nt = 0; nt < 8; ++nt) {
                const int col = nt * 8 + eb;
                v[2 * nt]     = red1[row * 65 + col]     + red2[row * 65 + col];
                v[2 * nt + 1] = red1[row * 65 + col + 1] + red2[row * 65 + col + 1];
            }

            float* lp = logits_out + (size_t)row_g * EXP;
#pragma unroll
            for (int nt = 0; nt < 8; ++nt)
                *(float2*)(lp + nt * 8 + eb) = make_float2(v[2 * nt], v[2 * nt + 1]);

            float v1 = v[0], v2 = -INFINITY, v3 = -INFINITY;
            int i1 = eb, i2 = 1 << 20, i3 = 1 << 20;
#pragma unroll
            for (int idx = 1; idx < 16; ++idx) {
                const int e = (idx >> 1) * 8 + eb + (idx & 1);
                const float val = v[idx];
                if (ranks_above(val, e, v1, i1)) {
                    v3 = v2; i3 = i2; v2 = v1; i2 = i1; v1 = val; i1 = e;
                } else if (ranks_above(val, e, v2, i2)) {
                    v3 = v2; i3 = i2; v2 = val; i2 = e;
                } else if (ranks_above(val, e, v3, i3)) {
                    v3 = val; i3 = e;
                }
            }
#pragma unroll
            for (int m = 1; m <= 2; m <<= 1) {
                const float b1 = __shfl_xor_sync(0xffffffffu, v1, m);
                const float b2 = __shfl_xor_sync(0xffffffffu, v2, m);
                const float b3 = __shfl_xor_sync(0xffffffffu, v3, m);
                const int j1 = __shfl_xor_sync(0xffffffffu, i1, m);
                const int j2 = __shfl_xor_sync(0xffffffffu, i2, m);
                const int j3 = __shfl_xor_sync(0xffffffffu, i3, m);
                const float bv[3] = {b1, b2, b3};
                const int bi[3] = {j1, j2, j3};
#pragma unroll
                for (int c2 = 0; c2 < 3; ++c2) {
                    const float val = bv[c2]; const int e = bi[c2];
                    if (ranks_above(val, e, v1, i1)) {
                        v3 = v2; i3 = i2; v2 = v1; i2 = i1; v1 = val; i1 = e;
                    } else if (ranks_above(val, e, v2, i2)) {
                        v3 = v2; i3 = i2; v2 = val; i2 = e;
                    } else if (ranks_above(val, e, v3, i3)) {
                        v3 = val; i3 = e;
                    }
                }
            }

            int sel1 = i1, sel2 = i2;

            const bool flag = (eb == 0) && (v2 - v3 < MARGIN_EPS);
            unsigned need = __ballot_sync(0xffffffffu, flag);
            while (need) {
                const int src = __ffs(need) - 1;
                need &= need - 1;
                const int rrow = __shfl_sync(0xffffffffu, row_g, src);
                int cand[3];
                cand[0] = __shfl_sync(0xffffffffu, i1, src);
                cand[1] = __shfl_sync(0xffffffffu, i2, src);
                cand[2] = __shfl_sync(0xffffffffu, i3, src);
                const float* xr = x + (size_t)rrow * KDIM;
                double dv[3];
#pragma unroll
                for (int cc = 0; cc < 3; ++cc) {
                    const int e = cand[cc];
                    double p0 = 0.0, p1 = 0.0, p2 = 0.0, p3 = 0.0;
                    for (int k = lane; k < KDIM; k += 128) {
                        p0 = fma((double)xr[k],      (double)W[(size_t)k * EXP + e],        p0);
                        p1 = fma((double)xr[k + 32], (double)W[(size_t)(k + 32) * EXP + e], p1);
                        p2 = fma((double)xr[k + 64], (double)W[(size_t)(k + 64) * EXP + e], p2);
                        p3 = fma((double)xr[k + 96], (double)W[(size_t)(k + 96) * EXP + e], p3);
                    }
                    double sd = (p0 + p1) + (p2 + p3);
#pragma unroll
                    for (int m = 1; m <= 16; m <<= 1)
                        sd += __shfl_xor_sync(0xffffffffu, sd, m);
                    dv[cc] = sd;
                }
                int ord[3] = {0, 1, 2};
#pragma unroll
                for (int a = 0; a < 2; ++a)
#pragma unroll
                    for (int b = 0; b < 2 - a; ++b) {
                        const int u = ord[b], w = ord[b + 1];
                        const bool above = (dv[u] > dv[w]) ||
                                           (dv[u] == dv[w] && cand[u] < cand[w]);
                        if (!above) { ord[b] = w; ord[b + 1] = u; }
                    }
                const int s1 = cand[ord[0]];
                const int s2 = (dv[ord[1]] - dv[ord[2]] < INVERT_TAU)
                                   ? cand[ord[2]] : cand[ord[1]];
                if ((lane >> 2) == (src >> 2)) { sel1 = s1; sel2 = s2; }
            }

            float ev[16];
            float ssum = 0.0f;
#pragma unroll
            for (int idx = 0; idx < 16; ++idx) {
                ev[idx] = expf(v[idx] - v1);
                ssum += ev[idx];
            }
            ssum += __shfl_xor_sync(0xffffffffu, ssum, 1);
            ssum += __shfl_xor_sync(0xffffffffu, ssum, 2);
            const float inv_s = 1.0f / ssum;

            float* yp = y_out + (size_t)row_g * EXP;
#pragma unroll
            for (int nt = 0; nt < 8; ++nt) {
                const int e0 = nt * 8 + eb, e1 = e0 + 1;
                float2 vy;
                vy.x = (e0 == sel1 || e0 == sel2) ? ev[2 * nt] * inv_s : 0.0f;
                vy.y = (e1 == sel1 || e1 == sel2) ? ev[2 * nt + 1] * inv_s : 0.0f;
                *(float2*)(yp + e0) = vy;
            }
        }
    }
}

extern "C" void kernel_launch(void* const* d_in, const int* in_sizes, int n_in,
                              void* d_out, int out_size) {
    const float* x = (const float*)d_in[0];
    const float* W = (const float*)d_in[1];
    float* out = (float*)d_out;

    const int M = in_sizes[0] / KDIM;          // 16384
    float* y_out = out;                        // first half: y
    float* logits_out = out + (size_t)M * EXP; // second half: logits

    prep_W_kernel<<<(EXP * KDIM) / 256, 256>>>(W);

    cudaFuncSetAttribute(gate_hmma_kernel,
                         cudaFuncAttributeMaxDynamicSharedMemorySize, SMEM_TOTAL);
    gate_hmma_kernel<<<M / BM, THREADS, SMEM_TOTAL>>>(x, W, y_out, logits_out);
}

// round 15
// speedup vs baseline: 1.0629x; 1.0629x over previous
#include <cuda_runtime.h>
#include <cuda_bf16.h>
#include <math.h>
#include <stdint.h>

// Gate_90426241450822: logits = x @ W ; y = softmax(logits) * top2_mask
// x: [M=16384, K=4096] fp32, W: [K=4096, E=64] fp32
// out: [y (M*64) | logits (M*64)] fp32
//
// R15 = R13 (best: 166us) + DUAL ACCUMULATORS: the 3 split-term HMMAs per
// output quad no longer form a serial 3-chain on one register quad;
// ca gets hh+lh (chain 2), cb gets hl (chain 1), merged at partial-dump.
// Everything else identical to R13: BM=64, 512 thr (4M x 2K x 2N warps),
// 3-stage cp.async, 2 CTAs/SM, epilogue with exact fp64 rescue
// (margin < 1e-4) + 1.2e-6 inversion window (R7-locked).

#define KDIM 4096
#define EXP 64
#define BM 64
#define BK 64
#define NT (KDIM / BK)        // 64 tiles
#define THREADS 512
#define STAGES 3

#define MARGIN_EPS 1e-4f
#define INVERT_TAU 1.2e-6

// stage layout (bytes)
#define A_STG 16384                      // 64 rows x 256B
#define B_ROWB 144                       // 64 bf16 (128B) padded to 144B
#define B_HALF (EXP * B_ROWB)            // 9216
#define OFF_BHI A_STG
#define OFF_BLO (A_STG + B_HALF)
#define STG_SZ (A_STG + 2 * B_HALF)      // 34816
#define SMEM_TOTAL (STAGES * STG_SZ)     // 104448 (covers 2x 16640B red)

__device__ __nv_bfloat16 g_Whi[EXP * KDIM];
__device__ __nv_bfloat16 g_Wlo[EXP * KDIM];

__device__ __forceinline__ uint32_t smem_u32(const void* p) {
    uint32_t a;
    asm("{ .reg .u64 t; cvta.to.shared.u64 t, %1; cvt.u32.u64 %0, t; }"
        : "=r"(a) : "l"(p));
    return a;
}
__device__ __forceinline__ void cp16(uint32_t dst, const void* src) {
    asm volatile("cp.async.cg.shared.global [%0], [%1], 16;"
                 :: "r"(dst), "l"(src) : "memory");
}
#define CP_COMMIT() asm volatile("cp.async.commit_group;" ::: "memory")
#define CP_WAIT1()  asm volatile("cp.async.wait_group 1;" ::: "memory")
#define CP_WAIT0()  asm volatile("cp.async.wait_group 0;" ::: "memory")

__device__ __forceinline__ float2 lds_f2(uint32_t addr) {
    float2 v;
    asm volatile("ld.shared.v2.f32 {%0,%1}, [%2];"
                 : "=f"(v.x), "=f"(v.y) : "r"(addr));
    return v;
}
__device__ __forceinline__ void ldsm_x4(uint32_t* r, uint32_t addr) {
    asm volatile("ldmatrix.sync.aligned.m8n8.x4.shared.b16 {%0,%1,%2,%3}, [%4];"
                 : "=r"(r[0]), "=r"(r[1]), "=r"(r[2]), "=r"(r[3]) : "r"(addr));
}
__device__ __forceinline__ void mma_bf16(float* c, const uint32_t* a,
                                         uint32_t b0, uint32_t b1) {
    asm volatile(
        "mma.sync.aligned.m16n8k16.row.col.f32.bf16.bf16.f32 "
        "{%0,%1,%2,%3}, {%4,%5,%6,%7}, {%8,%9}, {%0,%1,%2,%3};"
        : "+f"(c[0]), "+f"(c[1]), "+f"(c[2]), "+f"(c[3])
        : "r"(a[0]), "r"(a[1]), "r"(a[2]), "r"(a[3]), "r"(b0), "r"(b1));
}
__device__ __forceinline__ void split2(float2 f, uint32_t& hi, uint32_t& lo) {
    uint32_t h;
    asm("cvt.rn.bf16x2.f32 %0, %1, %2;" : "=r"(h) : "f"(f.y), "f"(f.x));
    const float h0 = __uint_as_float(h << 16);
    const float h1 = __uint_as_float(h & 0xffff0000u);
    const float r0 = f.x - h0;
    const float r1 = f.y - h1;
    asm("cvt.rn.bf16x2.f32 %0, %1, %2;" : "=r"(lo) : "f"(r1), "f"(r0));
    hi = h;
}
__device__ __forceinline__ bool ranks_above(float v1, int i1, float v2, int i2) {
    return (v1 > v2) || (v1 == v2 && i1 < i2);
}

// ---- W prep: split fp32 -> bf16 hi/lo, transpose to [E][K] ----
__global__ void prep_W_kernel(const float* __restrict__ W) {
    int idx = blockIdx.x * blockDim.x + threadIdx.x;
    int e = idx >> 12;
    int k = idx & (KDIM - 1);
    float v = W[(size_t)k * EXP + e];
    __nv_bfloat16 h = __float2bfloat16(v);
    g_Whi[idx] = h;
    g_Wlo[idx] = __float2bfloat16(v - __bfloat162float(h));
}

__global__ __launch_bounds__(THREADS, 2)
void gate_hmma_kernel(const float* __restrict__ x,
                      const float* __restrict__ W,
                      float* __restrict__ y_out,
                      float* __restrict__ logits_out) {
    extern __shared__ __align__(16) char smem[];
    const uint32_t sb = smem_u32(smem);
    const int tid = threadIdx.x;
    const int wid = tid >> 5;
    const int lane = tid & 31;
    const int mwarp = wid & 3;             // rows mwarp*16 .. +15
    const int khalf = (wid >> 2) & 1;      // k-steps {0,1} or {2,3}
    const int nhalf = wid >> 3;            // cols 0-31 or 32-63
    const int block_row = blockIdx.x * BM;

    // ---- producer constants (512 threads) ----
    const int p_arow = tid >> 3;               // A: 8 threads/row (64 rows)
    const int p_acb = (tid & 7) * 2;           // 2 chunks each
    const float* p_asrc = x + (size_t)(block_row + p_arow) * KDIM + p_acb * 4;
    const uint32_t p_aswz = (uint32_t)((p_arow & 3) << 1);
    const uint32_t p_adst = (uint32_t)(p_arow * 256);

    const int p_be = tid >> 3;                 // expert 0..63
    const int p_bp = tid & 7;                  // chunk 0..7
    const __nv_bfloat16* p_bh = g_Whi + (size_t)p_be * KDIM + p_bp * 8;
    const __nv_bfloat16* p_bl = g_Wlo + (size_t)p_be * KDIM + p_bp * 8;
    const uint32_t p_bdst = (uint32_t)(p_be * B_ROWB + p_bp * 16);

    // ---- consumer constants ----
    const uint32_t c_row1 = (uint32_t)((mwarp * 16 + (lane >> 2)) * 256);
    const uint32_t c_swz = (uint32_t)(((lane >> 2) & 3) << 1);
    const int kb = (lane & 3) * 2;
    const int bg = lane >> 3;
    const uint32_t b_ldoff =
        (uint32_t)(((bg >> 1) * 8 + (lane & 7)) * B_ROWB + (bg & 1) * 16);

    float ca[4][4], cb[4][4];
#pragma unroll
    for (int i = 0; i < 4; ++i)
#pragma unroll
        for (int j = 0; j < 4; ++j) { ca[i][j] = 0.0f; cb[i][j] = 0.0f; }

    auto issue_tile = [&](int t) {
        const uint32_t stg = sb + (uint32_t)(t % STAGES) * STG_SZ;
        const int k0 = t * BK;
        const float* asrc = p_asrc + k0;
#pragma unroll
        for (int j = 0; j < 2; ++j) {
            const uint32_t cidx = (uint32_t)(p_acb + j);
            cp16(stg + p_adst + ((cidx ^ p_aswz) << 4), asrc + j * 4);
        }
        cp16(stg + OFF_BHI + p_bdst, p_bh + k0);
        cp16(stg + OFF_BLO + p_bdst, p_bl + k0);
        CP_COMMIT();
    };

    issue_tile(0);
    issue_tile(1);

    for (int t = 0; t < NT; ++t) {
        if (t + 2 < NT) CP_WAIT1(); else CP_WAIT0();
        __syncthreads();
        if (t + 2 < NT) issue_tile(t + 2);

        const uint32_t stg = sb + (uint32_t)(t % STAGES) * STG_SZ;

#pragma unroll
        for (int kk = 0; kk < 2; ++kk) {
            const int ks = khalf * 2 + kk;
            const int k0 = ks * 16 + kb;
            const uint32_t off0 =
                (((uint32_t)(k0 >> 2) ^ c_swz) << 4) + (uint32_t)((k0 & 3) * 4);
            const uint32_t off8 =
                (((uint32_t)((k0 + 8) >> 2) ^ c_swz) << 4) + (uint32_t)((k0 & 3) * 4);
            uint32_t ahi[4], alo[4];
            split2(lds_f2(stg + c_row1 + off0),        ahi[0], alo[0]);
            split2(lds_f2(stg + c_row1 + 2048 + off0), ahi[1], alo[1]);
            split2(lds_f2(stg + c_row1 + off8),        ahi[2], alo[2]);
            split2(lds_f2(stg + c_row1 + 2048 + off8), ahi[3], alo[3]);

#pragma unroll
            for (int npl = 0; npl < 2; ++npl) {
                const int np = nhalf * 2 + npl;
                uint32_t bh[4], bl[4];
                const uint32_t bo = b_ldoff + (uint32_t)(np * 16 * B_ROWB + ks * 32);
                ldsm_x4(bh, stg + OFF_BHI + bo);
                ldsm_x4(bl, stg + OFF_BLO + bo);
                // dual accumulators: ca <- hh (+ lh later), cb <- hl
                mma_bf16(ca[2 * npl],     ahi, bh[0], bh[1]);
                mma_bf16(cb[2 * npl],     ahi, bl[0], bl[1]);
                mma_bf16(ca[2 * npl + 1], ahi, bh[2], bh[3]);
                mma_bf16(cb[2 * npl + 1], ahi, bl[2], bl[3]);
                mma_bf16(ca[2 * npl],     alo, bh[0], bh[1]);
                mma_bf16(ca[2 * npl + 1], alo, bh[2], bh[3]);
            }
        }
    }

    // red buffers overlay stage smem -> barrier before reuse
    __syncthreads();

    // ---- dump partials (ca+cb merged): red1 = khalf0, red2 = khalf1 ----
    float* red1 = (float*)smem;                // 64 x 65 fp32
    float* red2 = red1 + 64 * 65;
    {
        float* buf = khalf ? red2 : red1;
        const int q = lane >> 2;
        const int eb = (lane & 3) * 2;
#pragma unroll
        for (int i = 0; i < 4; ++i)
#pragma unroll
            for (int j = 0; j < 4; ++j) {
                const int row = mwarp * 16 + q + ((j >> 1) << 3);
                const int col = nhalf * 32 + i * 8 + eb + (j & 1);
                buf[row * 65 + col] = ca[i][j] + cb[i][j];
            }
    }
    __syncthreads();

    // ---- epilogue (R9-R13 validated) on warps 0-3 ----
    if (wid < 4) {
        const int q = lane >> 2;
        const int eb = (lane & 3) * 2;
#pragma unroll
        for (int h = 0; h < 2; ++h) {
            const int row = wid * 16 + q + h * 8;
            const int row_g = block_row + row;
            float v[16];
#pragma unroll
            for (int nt = 0; nt < 8; ++nt) {
                const int col = nt * 8 + eb;
                v[2 * nt]     = red1[row * 65 + col]     + red2[row * 65 + col];
                v[2 * nt + 1] = red1[row * 65 + col + 1] + red2[row * 65 + col + 1];
            }

            float* lp = logits_out + (size_t)row_g * EXP;
#pragma unroll
            for (int nt = 0; nt < 8; ++nt)
                *(float2*)(lp + nt * 8 + eb) = make_float2(v[2 * nt], v[2 * nt + 1]);

            float v1 = v[0], v2 = -INFINITY, v3 = -INFINITY;
            int i1 = eb, i2 = 1 << 20, i3 = 1 << 20;
#pragma unroll
            for (int idx = 1; idx < 16; ++idx) {
                const int e = (idx >> 1) * 8 + eb + (idx & 1);
                const float val = v[idx];
                if (ranks_above(val, e, v1, i1)) {
                    v3 = v2; i3 = i2; v2 = v1; i2 = i1; v1 = val; i1 = e;
                } else if (ranks_above(val, e, v2, i2)) {
                    v3 = v2; i3 = i2; v2 = val; i2 = e;
                } else if (ranks_above(val, e, v3, i3)) {
                    v3 = val; i3 = e;
                }
            }
#pragma unroll
            for (int m = 1; m <= 2; m <<= 1) {
                const float b1 = __shfl_xor_sync(0xffffffffu, v1, m);
                const float b2 = __shfl_xor_sync(0xffffffffu, v2, m);
                const float b3 = __shfl_xor_sync(0xffffffffu, v3, m);
                const int j1 = __shfl_xor_sync(0xffffffffu, i1, m);
                const int j2 = __shfl_xor_sync(0xffffffffu, i2, m);
                const int j3 = __shfl_xor_sync(0xffffffffu, i3, m);
                const float bv[3] = {b1, b2, b3};
                const int bi[3] = {j1, j2, j3};
#pragma unroll
                for (int c2 = 0; c2 < 3; ++c2) {
                    const float val = bv[c2]; const int e = bi[c2];
                    if (ranks_above(val, e, v1, i1)) {
                        v3 = v2; i3 = i2; v2 = v1; i2 = i1; v1 = val; i1 = e;
                    } else if (ranks_above(val, e, v2, i2)) {
                        v3 = v2; i3 = i2; v2 = val; i2 = e;
                    } else if (ranks_above(val, e, v3, i3)) {
                        v3 = val; i3 = e;
                    }
                }
            }

            int sel1 = i1, sel2 = i2;

            const bool flag = (eb == 0) && (v2 - v3 < MARGIN_EPS);
            unsigned need = __ballot_sync(0xffffffffu, flag);
            while (need) {
                const int src = __ffs(need) - 1;
                need &= need - 1;
                const int rrow = __shfl_sync(0xffffffffu, row_g, src);
                int cand[3];
                cand[0] = __shfl_sync(0xffffffffu, i1, src);
                cand[1] = __shfl_sync(0xffffffffu, i2, src);
                cand[2] = __shfl_sync(0xffffffffu, i3, src);
                const float* xr = x + (size_t)rrow * KDIM;
                double dv[3];
#pragma unroll
                for (int cc = 0; cc < 3; ++cc) {
                    const int e = cand[cc];
                    double p0 = 0.0, p1 = 0.0, p2 = 0.0, p3 = 0.0;
                    for (int k = lane; k < KDIM; k += 128) {
                        p0 = fma((double)xr[k],      (double)W[(size_t)k * EXP + e],        p0);
                        p1 = fma((double)xr[k + 32], (double)W[(size_t)(k + 32) * EXP + e], p1);
                        p2 = fma((double)xr[k + 64], (double)W[(size_t)(k + 64) * EXP + e], p2);
                        p3 = fma((double)xr[k + 96], (double)W[(size_t)(k + 96) * EXP + e], p3);
                    }
                    double sd = (p0 + p1) + (p2 + p3);
#pragma unroll
                    for (int m = 1; m <= 16; m <<= 1)
                        sd += __shfl_xor_sync(0xffffffffu, sd, m);
                    dv[cc] = sd;
                }
                int ord[3] = {0, 1, 2};
#pragma unroll
                for (int a = 0; a < 2; ++a)
#pragma unroll
                    for (int b = 0; b < 2 - a; ++b) {
                        const int u = ord[b], w = ord[b + 1];
                        const bool above = (dv[u] > dv[w]) ||
                                           (dv[u] == dv[w] && cand[u] < cand[w]);
                        if (!above) { ord[b] = w; ord[b + 1] = u; }
                    }
                const int s1 = cand[ord[0]];
                const int s2 = (dv[ord[1]] - dv[ord[2]] < INVERT_TAU)
                                   ? cand[ord[2]] : cand[ord[1]];
                if ((lane >> 2) == (src >> 2)) { sel1 = s1; sel2 = s2; }
            }

            float ev[16];
            float ssum = 0.0f;
#pragma unroll
            for (int idx = 0; idx < 16; ++idx) {
                ev[idx] = expf(v[idx] - v1);
                ssum += ev[idx];
            }
            ssum += __shfl_xor_sync(0xffffffffu, ssum, 1);
            ssum += __shfl_xor_sync(0xffffffffu, ssum, 2);
            const float inv_s = 1.0f / ssum;

            float* yp = y_out + (size_t)row_g * EXP;
#pragma unroll
            for (int nt = 0; nt < 8; ++nt) {
                const int e0 = nt * 8 + eb, e1 = e0 + 1;
                float2 vy;
                vy.x = (e0 == sel1 || e0 == sel2) ? ev[2 * nt] * inv_s : 0.0f;
                vy.y = (e1 == sel1 || e1 == sel2) ? ev[2 * nt + 1] * inv_s : 0.0f;
                *(float2*)(yp + e0) = vy;
            }
        }
    }
}

extern "C" void kernel_launch(void* const* d_in, const int* in_sizes, int n_in,
                              void* d_out, int out_size) {
    const float* x = (const float*)d_in[0];
    const float* W = (const float*)d_in[1];
    float* out = (float*)d_out;

    const int M = in_sizes[0] / KDIM;          // 16384
    float* y_out = out;                        // first half: y
    float* logits_out = out + (size_t)M * EXP; // second half: logits

    prep_W_kernel<<<(EXP * KDIM) / 256, 256>>>(W);

    cudaFuncSetAttribute(gate_hmma_kernel,
                         cudaFuncAttributeMaxDynamicSharedMemorySize, SMEM_TOTAL);
    gate_hmma_kernel<<<M / BM, THREADS, SMEM_TOTAL>>>(x, W, y_out, logits_out);
}